// round 13
// baseline (speedup 1.0000x reference)
#include <cuda_runtime.h>
#include <cuda_bf16.h>
#include <math.h>

#define BB 4
#define SS 4096
#define DD 1024
#define HH 128
#define MM 256
#define RR 64
#define CC 64
#define NCH 64

static constexpr size_t SZ_BSH  = (size_t)BB*SS*HH;
static constexpr size_t OFF_KRAW  = 0;
static constexpr size_t OFF_VRAW  = OFF_KRAW  + SZ_BSH;
static constexpr size_t OFF_K     = OFF_VRAW  + SZ_BSH;
static constexpr size_t OFF_V     = OFF_K     + SZ_BSH;
static constexpr size_t OFF_DELTA = OFF_V     + SZ_BSH;
static constexpr size_t OFF_COMB  = OFF_DELTA + SZ_BSH;
static constexpr size_t OFF_RD    = OFF_COMB  + SZ_BSH;
static constexpr size_t OFF_GATE  = OFF_RD    + (size_t)BB*SS*RR;
static constexpr size_t OFF_ETA   = OFF_GATE  + (size_t)BB*SS*DD;
static constexpr size_t OFF_ALPHA = OFF_ETA   + (size_t)BB*NCH*HH;
static constexpr size_t OFF_AW    = OFF_ALPHA + (size_t)BB*NCH*HH;
static constexpr size_t OFF_EW    = OFF_AW    + BB*NCH;
static constexpr size_t OFF_W1    = OFF_EW    + BB*NCH;
static constexpr size_t OFF_W2T   = OFF_W1    + (size_t)BB*MM*HH;
static constexpr size_t OFF_B1    = OFF_W2T   + 2ull*BB*MM*HH;
static constexpr size_t OFF_B2    = OFF_B1    + BB*MM;
static constexpr size_t OFF_ACT   = OFF_B2    + BB*HH;
static constexpr size_t OFF_USP   = OFF_ACT   + (size_t)BB*CC*MM;
static constexpr size_t OFF_AM    = OFF_USP   + BB*8*HH;
static constexpr size_t TOTAL_F   = OFF_AM    + 2ull*BB*MM;

__device__ float g_blob[TOTAL_F];

__device__ __forceinline__ float gelu_exact(float x) {
    return 0.5f * x * (1.0f + erff(x * 0.7071067811865476f));
}
__device__ __forceinline__ float softplus_f(float x) {
    return fmaxf(x, 0.0f) + log1pf(expf(-fabsf(x)));
}
__device__ __forceinline__ float sigmoid_f(float x) {
    return 1.0f / (1.0f + expf(-x));
}
__device__ __forceinline__ float warpSum(float v) {
    #pragma unroll
    for (int o = 16; o > 0; o >>= 1) v += __shfl_down_sync(0xffffffffu, v, o);
    return v;
}

// ---------------- generic fp32 SGEMM: C[M,N]=A[M,K]@B[K,N] ----------------
// 128x128 tile, BK=16, 256 threads, 8x8 per thread. M%128==0, K%16==0 required.
// epi: 0 none, 1 softplus, 2 multiply by sigmoid(gate[r*N+c]).
__global__ __launch_bounds__(256, 2)
void sgemm_kernel(const float* __restrict__ A, const float* __restrict__ B,
                  float* __restrict__ C, int M, int N, int K,
                  const float* __restrict__ gate, int epi)
{
    __shared__ float As[16][128];
    __shared__ float Bs[16][128];
    const int tid = threadIdx.x;
    const int row0 = blockIdx.y * 128;
    const int col0 = blockIdx.x * 128;
    const int tx = tid & 15, ty = tid >> 4;

    float acc[8][8];
    #pragma unroll
    for (int i = 0; i < 8; i++)
        #pragma unroll
        for (int j = 0; j < 8; j++) acc[i][j] = 0.f;

    const int aRow = tid >> 2;
    const int aK   = (tid & 3) * 4;

    for (int k0 = 0; k0 < K; k0 += 16) {
        #pragma unroll
        for (int i = 0; i < 2; i++) {
            int r = aRow + i * 64;
            float4 v = *(const float4*)(A + (size_t)(row0 + r) * K + k0 + aK);
            As[aK + 0][r] = v.x; As[aK + 1][r] = v.y;
            As[aK + 2][r] = v.z; As[aK + 3][r] = v.w;
        }
        #pragma unroll
        for (int i = 0; i < 8; i++) {
            int idx = tid + i * 256;
            int kk = idx >> 7, c = idx & 127;
            float v = 0.f;
            if (col0 + c < N) v = B[(size_t)(k0 + kk) * N + col0 + c];
            Bs[kk][c] = v;
        }
        __syncthreads();
        #pragma unroll
        for (int kk = 0; kk < 16; kk++) {
            float a[8], b[8];
            #pragma unroll
            for (int i = 0; i < 8; i++) a[i] = As[kk][ty * 8 + i];
            #pragma unroll
            for (int j = 0; j < 8; j++) b[j] = Bs[kk][tx * 8 + j];
            #pragma unroll
            for (int i = 0; i < 8; i++)
                #pragma unroll
                for (int j = 0; j < 8; j++) acc[i][j] = fmaf(a[i], b[j], acc[i][j]);
        }
        __syncthreads();
    }
    #pragma unroll
    for (int i = 0; i < 8; i++) {
        int r = row0 + ty * 8 + i;
        #pragma unroll
        for (int j = 0; j < 8; j++) {
            int c = col0 + tx * 8 + j;
            if (c < N) {
                float v = acc[i][j];
                if (epi == 1)      v = softplus_f(v);
                else if (epi == 2) v *= sigmoid_f(gate[(size_t)r * N + c]);
                C[(size_t)r * N + c] = v;
            }
        }
    }
}

// ---------------- eta/alpha at chunk-last rows only ----------------
__global__ void etaalpha_kernel(const float* __restrict__ x,
    const float* __restrict__ We1, const float* __restrict__ We2,
    const float* __restrict__ Wa1, const float* __restrict__ Wa2,
    float* __restrict__ eta_last, float* __restrict__ alpha_last,
    float* __restrict__ awb, float* __restrict__ ewb)
{
    const int bn = blockIdx.x;              // b*64+n
    const int b = bn >> 6, n = bn & 63;
    const float* xr = x + ((size_t)b * SS + n * CC + (CC - 1)) * DD;
    const int tid = threadIdx.x;            // 128 threads
    __shared__ float re2[2][64], ra2[2][64];
    __shared__ float re[64], ra[64];
    __shared__ float red[4];

    const int r = tid & 63, part = tid >> 6;
    float se = 0.f, sa = 0.f;
    for (int d = part * 512; d < part * 512 + 512; d++) {
        float xv = xr[d];
        se = fmaf(xv, We1[d * RR + r], se);
        sa = fmaf(xv, Wa1[d * RR + r], sa);
    }
    re2[part][r] = se; ra2[part][r] = sa;
    __syncthreads();
    if (tid < 64) { re[tid] = re2[0][tid] + re2[1][tid]; ra[tid] = ra2[0][tid] + ra2[1][tid]; }
    __syncthreads();

    float ee = 0.f, aa = 0.f;
    #pragma unroll 8
    for (int rr = 0; rr < 64; rr++) {
        ee = fmaf(re[rr], We2[rr * HH + tid], ee);
        aa = fmaf(ra[rr], Wa2[rr * HH + tid], aa);
    }
    float ev = softplus_f(ee);
    float av = sigmoid_f(aa);
    eta_last[bn * HH + tid] = ev;
    alpha_last[bn * HH + tid] = av;

    float s = warpSum(av);
    if ((tid & 31) == 0) red[tid >> 5] = s;
    __syncthreads();
    if (tid == 0) awb[bn] = (red[0] + red[1] + red[2] + red[3]) * (1.f / HH);
    __syncthreads();
    s = warpSum(ev);
    if ((tid & 31) == 0) red[tid >> 5] = s;
    __syncthreads();
    if (tid == 0) ewb[bn] = (red[0] + red[1] + red[2] + red[3]) * (1.f / HH);
}

// ---------------- causal dwconv(4) for k,v + LN(k) ----------------
__device__ __forceinline__ float blockSum128(float v, float* red) {
    v = warpSum(v);
    int lane = threadIdx.x & 31, w = threadIdx.x >> 5;
    if (lane == 0) red[w] = v;
    __syncthreads();
    float s = red[0] + red[1] + red[2] + red[3];
    __syncthreads();
    return s;
}

__global__ void convln_kernel(const float* __restrict__ kraw, const float* __restrict__ vraw,
    const float* __restrict__ conv_w, const float* __restrict__ conv_b,
    const float* __restrict__ kn_g, const float* __restrict__ kn_b,
    float* __restrict__ kout, float* __restrict__ vout)
{
    const int bs = blockIdx.x;
    const int s = bs & (SS - 1);
    const int h = threadIdx.x;
    const size_t base = (size_t)bs * HH + h;
    __shared__ float red[4];

    float w0 = conv_w[h * 4 + 0], w1 = conv_w[h * 4 + 1];
    float w2 = conv_w[h * 4 + 2], w3 = conv_w[h * 4 + 3];
    float cb = conv_b[h];
    float kc = cb, vc = cb;
    kc = fmaf(w3, kraw[base], kc);            vc = fmaf(w3, vraw[base], vc);
    if (s >= 1) { kc = fmaf(w2, kraw[base - HH],   kc); vc = fmaf(w2, vraw[base - HH],   vc); }
    if (s >= 2) { kc = fmaf(w1, kraw[base - 2*HH], kc); vc = fmaf(w1, vraw[base - 2*HH], vc); }
    if (s >= 3) { kc = fmaf(w0, kraw[base - 3*HH], kc); vc = fmaf(w0, vraw[base - 3*HH], vc); }

    float mean = blockSum128(kc, red) * (1.f / HH);
    float d = kc - mean;
    float var = blockSum128(d * d, red) * (1.f / HH);
    kout[base] = d * rsqrtf(var + 1e-5f) * kn_g[h] + kn_b[h];
    vout[base] = vc;
}

// ---------------- state init ----------------
__global__ void init_state_kernel(const float* __restrict__ mW1, const float* __restrict__ mb1,
                                  const float* __restrict__ mW2, const float* __restrict__ mb2,
                                  float* __restrict__ W1, float* __restrict__ W2T,
                                  float* __restrict__ b1, float* __restrict__ b2)
{
    int i = blockIdx.x * 256 + threadIdx.x;
    if (i < BB * MM * HH) {
        int mh = i % (MM * HH);
        int m = mh >> 7, h = mh & 127;
        W1[i]  = mW1[mh];
        W2T[i] = mW2[h * MM + m];
    }
    if (i < BB * MM) b1[i] = mb1[i % MM];
    if (i < BB * HH) b2[i] = mb2[i % HH];
}

// ---------------- scan kernel A: deferred state update + inter/gelu ----------------
// grid (20, B). bx 0..15: inter blocks (16 m-cols each). bx 16..19: W2T update.
__global__ __launch_bounds__(256)
void chunkA_kernel(int t,
    const float* __restrict__ kbuf, const float* __restrict__ eta_last,
    const float* __restrict__ alpha_last, const float* __restrict__ awb,
    const float* __restrict__ ewb,
    float* __restrict__ W1, float* __restrict__ W2T,
    float* __restrict__ b1, float* __restrict__ b2,
    float* __restrict__ act, const float* __restrict__ us_part,
    float* __restrict__ am)
{
    const int b = blockIdx.y;
    const int bx = blockIdx.x;
    const int tid = threadIdx.x;

    if (bx >= 16) {                      // W2T + b2 deferred update
        if (t == 0) return;
        __shared__ float us_u[HH];
        if (tid < HH) {
            float s = 0.f;
            #pragma unroll
            for (int rb = 0; rb < 8; rb++) s += us_part[(b * 8 + rb) * HH + tid];
            us_u[tid] = s * (1.f / CC);
        }
        __syncthreads();
        const float awv = awb[b * NCH + (t - 1)];
        const float ewv = ewb[b * NCH + (t - 1)];
        const int slice = bx - 16;
        const float* oldW2 = W2T + ((size_t)(((t - 1) & 1) * BB + b)) * (MM * HH);
        float*       newW2 = W2T + ((size_t)(((t)     & 1) * BB + b)) * (MM * HH);
        const float* amo = am + ((t - 1) & 1) * (BB * MM) + b * MM;
        for (int i = tid; i < 64 * HH; i += 256) {
            int m = slice * 64 + (i >> 7);
            int h = i & 127;
            newW2[m * HH + h] = awv * oldW2[m * HH + h] - ewv * us_u[h] * amo[m];
        }
        if (slice == 0 && tid < HH) {
            float ab = alpha_last[(b * NCH + t - 1) * HH + tid];
            float eb = eta_last[(b * NCH + t - 1) * HH + tid];
            b2[b * HH + tid] = ab * b2[b * HH + tid] - eb * us_u[tid];
        }
        return;
    }

    // ---- inter block ----
    __shared__ float W1s[16][129];
    __shared__ float kcs[CC][HH];
    __shared__ float b1s[16];
    __shared__ float us_s[HH];
    __shared__ float sus2_s;
    __shared__ float amred[16][17];

    const int m0 = bx * 16;
    float* W1g = W1 + (size_t)b * (MM * HH) + m0 * HH;
    float* b1g = b1 + b * MM + m0;

    if (t == 0) {
        for (int i = tid; i < 16 * HH; i += 256) W1s[i >> 7][i & 127] = W1g[i];
        if (tid < 16) b1s[tid] = b1g[tid];
    } else {
        if (tid < HH) {
            float s = 0.f;
            #pragma unroll
            for (int rb = 0; rb < 8; rb++) s += us_part[(b * 8 + rb) * HH + tid];
            us_s[tid] = s * (1.f / CC);
        }
        __syncthreads();
        if (tid < 32) {
            float s = 0.f;
            for (int i = tid; i < HH; i += 32) s += us_s[i] * us_s[i];
            s = warpSum(s);
            if (tid == 0) sus2_s = s;
        }
        __syncthreads();
        const float awv = awb[b * NCH + (t - 1)];
        const float ewv = ewb[b * NCH + (t - 1)];
        const float sus2 = sus2_s;
        const float* amo = am + ((t - 1) & 1) * (BB * MM) + b * MM + m0;
        for (int i = tid; i < 16 * HH; i += 256) {
            int m = i >> 7, h = i & 127;
            float w = awv * W1g[i] - ewv * amo[m] * us_s[h];
            W1g[i] = w;
            W1s[m][h] = w;
        }
        // b1 update: b1u[m] = aw*sum_h us*W2old[m,h] - ew*sus2*am[m]
        const float* oldW2 = W2T + ((size_t)(((t - 1) & 1) * BB + b)) * (MM * HH);
        int lane = tid & 31, wp = tid >> 5;
        #pragma unroll
        for (int q = 0; q < 2; q++) {
            int mm = wp * 2 + q;
            int m = m0 + mm;
            float s = 0.f;
            #pragma unroll
            for (int k = 0; k < 4; k++) {
                int h = lane + k * 32;
                s = fmaf(us_s[h], oldW2[m * HH + h], s);
            }
            s = warpSum(s);
            if (lane == 0) {
                float b1u = awv * s - ewv * sus2 * amo[mm];
                float nb1 = awv * b1g[mm] - ewv * b1u;
                b1g[mm] = nb1;
                b1s[mm] = nb1;
            }
        }
    }
    __syncthreads();

    const float* kc = kbuf + ((size_t)b * SS + t * CC) * HH;
    for (int i = tid; i < CC * HH; i += 256) kcs[i >> 7][i & 127] = kc[i];
    __syncthreads();

    const int m  = tid & 15;
    const int rg = tid >> 4;      // 16 groups of 4 rows
    float a0 = 0.f, a1 = 0.f, a2 = 0.f, a3 = 0.f;
    #pragma unroll 4
    for (int h = 0; h < HH; h++) {
        float w = W1s[m][h];
        a0 = fmaf(kcs[rg * 4 + 0][h], w, a0);
        a1 = fmaf(kcs[rg * 4 + 1][h], w, a1);
        a2 = fmaf(kcs[rg * 4 + 2][h], w, a2);
        a3 = fmaf(kcs[rg * 4 + 3][h], w, a3);
    }
    const float b1v = b1s[m];
    float vals[4] = {a0, a1, a2, a3};
    float amp = 0.f;
    float* actp = act + (size_t)b * (CC * MM) + (size_t)(rg * 4) * MM + m0 + m;
    #pragma unroll
    for (int i = 0; i < 4; i++) {
        float g = gelu_exact(vals[i] + b1v);
        actp[(size_t)i * MM] = g;
        amp += g;
    }
    amred[m][rg] = amp;
    __syncthreads();
    if (tid < 16) {
        float s = 0.f;
        #pragma unroll
        for (int r = 0; r < 16; r++) s += amred[tid][r];
        am[(t & 1) * (BB * MM) + b * MM + m0 + tid] = s * (1.f / CC);
    }
}

// ---------------- scan kernel B: out = act@W2T + b2, grad, us partials ----------------
// grid (8, B): 8 row-groups of 8 rows. 256 threads: h = tid&127, half = tid>>7 (4 rows).
__global__ __launch_bounds__(256)
void chunkB_kernel(int t,
    const float* __restrict__ vbuf, const float* __restrict__ delta,
    const float* __restrict__ act, const float* __restrict__ W2T,
    const float* __restrict__ b2,
    float* __restrict__ comb, float* __restrict__ us_part)
{
    const int b = blockIdx.y;
    const int rg = blockIdx.x;
    const int tid = threadIdx.x;
    const int h = tid & 127;
    const int half = tid >> 7;

    __shared__ float acts[8][MM];
    __shared__ float enred[8][4];
    __shared__ float us_s[HH];

    const float* actg = act + (size_t)b * (CC * MM) + (size_t)(rg * 8) * MM;
    for (int i = tid; i < 8 * MM; i += 256) acts[i >> 8][i & 255] = actg[i];
    __syncthreads();

    const float* w2 = W2T + ((size_t)((t & 1) * BB + b)) * (MM * HH);
    float o0 = 0.f, o1 = 0.f, o2 = 0.f, o3 = 0.f;
    const int r0 = half * 4;
    #pragma unroll 8
    for (int m = 0; m < MM; m++) {
        float w = __ldg(w2 + (size_t)m * HH + h);
        o0 = fmaf(acts[r0 + 0][m], w, o0);
        o1 = fmaf(acts[r0 + 1][m], w, o1);
        o2 = fmaf(acts[r0 + 2][m], w, o2);
        o3 = fmaf(acts[r0 + 3][m], w, o3);
    }
    const float b2v = b2[b * HH + h];
    float out[4] = {o0 + b2v, o1 + b2v, o2 + b2v, o3 + b2v};

    const size_t rowbase = (size_t)b * SS + (size_t)t * CC + rg * 8 + r0;
    float err[4];
    #pragma unroll
    for (int i = 0; i < 4; i++) {
        size_t idx = (rowbase + i) * HH + h;
        comb[idx] = out[i];
        err[i] = out[i] - vbuf[idx];
        float e2 = warpSum(err[i] * err[i]);
        if ((tid & 31) == 0) enred[r0 + i][(tid >> 5) & 3] = e2;
    }
    __syncthreads();

    float gs = 0.f;
    #pragma unroll
    for (int i = 0; i < 4; i++) {
        float en = sqrtf(enred[r0 + i][0] + enred[r0 + i][1] +
                         enred[r0 + i][2] + enred[r0 + i][3]);
        float dc = delta[(rowbase + i) * HH + h];
        float g = (en > dc) ? dc * err[i] / (en + 1e-9f) : err[i];
        gs += g;
    }
    if (half == 0) us_s[h] = gs;
    __syncthreads();
    if (half == 1) us_part[(b * 8 + rg) * HH + h] = us_s[h] + gs;
}

// ---------------- launch ----------------
extern "C" void kernel_launch(void* const* d_in, const int* in_sizes, int n_in,
                              void* d_out, int out_size)
{
    const float* x      = (const float*)d_in[0];
    const float* Wk     = (const float*)d_in[2];
    const float* Wv     = (const float*)d_in[3];
    const float* Wo     = (const float*)d_in[4];
    const float* Wg     = (const float*)d_in[5];
    const float* We1    = (const float*)d_in[6];
    const float* We2    = (const float*)d_in[7];
    const float* Wd1    = (const float*)d_in[8];
    const float* Wd2    = (const float*)d_in[9];
    const float* Wa1    = (const float*)d_in[10];
    const float* Wa2    = (const float*)d_in[11];
    const float* conv_w = (const float*)d_in[12];
    const float* conv_b = (const float*)d_in[13];
    const float* kn_g   = (const float*)d_in[16];
    const float* kn_b   = (const float*)d_in[17];
    const float* mW1    = (const float*)d_in[18];
    const float* mb1    = (const float*)d_in[19];
    const float* mW2    = (const float*)d_in[20];
    const float* mb2    = (const float*)d_in[21];
    float* out = (float*)d_out;

    float* blob = nullptr;
    cudaGetSymbolAddress((void**)&blob, g_blob);

    float* kraw   = blob + OFF_KRAW;
    float* vraw   = blob + OFF_VRAW;
    float* kbuf   = blob + OFF_K;
    float* vbuf   = blob + OFF_V;
    float* delta  = blob + OFF_DELTA;
    float* comb   = blob + OFF_COMB;
    float* rd     = blob + OFF_RD;
    float* gate   = blob + OFF_GATE;
    float* eta_l  = blob + OFF_ETA;
    float* alph_l = blob + OFF_ALPHA;
    float* awb    = blob + OFF_AW;
    float* ewb    = blob + OFF_EW;
    float* W1     = blob + OFF_W1;
    float* W2T    = blob + OFF_W2T;
    float* b1     = blob + OFF_B1;
    float* b2     = blob + OFF_B2;
    float* act    = blob + OFF_ACT;
    float* usp    = blob + OFF_USP;
    float* am     = blob + OFF_AM;

    const int MROWS = BB * SS;          // 16384
    dim3 blk(256);

    // eta/alpha at chunk-last rows
    etaalpha_kernel<<<BB * NCH, 128>>>(x, We1, We2, Wa1, Wa2, eta_l, alph_l, awb, ewb);

    // projections
    sgemm_kernel<<<dim3(1, MROWS / 128), blk>>>(x, Wk, kraw, MROWS, HH, DD, nullptr, 0);
    sgemm_kernel<<<dim3(1, MROWS / 128), blk>>>(x, Wv, vraw, MROWS, HH, DD, nullptr, 0);
    sgemm_kernel<<<dim3(1, MROWS / 128), blk>>>(x, Wd1, rd,  MROWS, RR, DD, nullptr, 0);
    sgemm_kernel<<<dim3(1, MROWS / 128), blk>>>(rd, Wd2, delta, MROWS, HH, RR, nullptr, 1);
    sgemm_kernel<<<dim3(DD / 128, MROWS / 128), blk>>>(x, Wg, gate, MROWS, DD, DD, nullptr, 0);

    // conv + LN
    convln_kernel<<<BB * SS, HH>>>(kraw, vraw, conv_w, conv_b, kn_g, kn_b, kbuf, vbuf);

    // init memory state
    init_state_kernel<<<(BB * MM * HH + 255) / 256, 256>>>(mW1, mb1, mW2, mb2, W1, W2T, b1, b2);

    // sequential scan over 64 chunks
    for (int t = 0; t < NCH; t++) {
        chunkA_kernel<<<dim3(20, BB), blk>>>(t, kbuf, eta_l, alph_l, awb, ewb,
                                             W1, W2T, b1, b2, act, usp, am);
        chunkB_kernel<<<dim3(8, BB), blk>>>(t, vbuf, delta, act, W2T, b2, comb, usp);
    }

    // final: out = (comb @ Wo) * sigmoid(gate)
    sgemm_kernel<<<dim3(DD / 128, MROWS / 128), blk>>>(comb, Wo, out, MROWS, DD, HH, gate, 2);
}

// round 15
// speedup vs baseline: 1.0026x; 1.0026x over previous
#include <cuda_runtime.h>
#include <cuda_bf16.h>
#include <math.h>

#define BB 4
#define SS 4096
#define DD 1024
#define HH 128
#define MM 256
#define RR 64
#define CC 64
#define NCH 64

static constexpr size_t SZ_BSH  = (size_t)BB*SS*HH;
static constexpr size_t OFF_KRAW  = 0;
static constexpr size_t OFF_VRAW  = OFF_KRAW  + SZ_BSH;
static constexpr size_t OFF_K     = OFF_VRAW  + SZ_BSH;
static constexpr size_t OFF_V     = OFF_K     + SZ_BSH;
static constexpr size_t OFF_DELTA = OFF_V     + SZ_BSH;
static constexpr size_t OFF_COMB  = OFF_DELTA + SZ_BSH;
static constexpr size_t OFF_RD    = OFF_COMB  + SZ_BSH;
static constexpr size_t OFF_GATE  = OFF_RD    + (size_t)BB*SS*RR;
static constexpr size_t OFF_ETA   = OFF_GATE  + (size_t)BB*SS*DD;
static constexpr size_t OFF_ALPHA = OFF_ETA   + (size_t)BB*NCH*HH;
static constexpr size_t OFF_AW    = OFF_ALPHA + (size_t)BB*NCH*HH;
static constexpr size_t OFF_EW    = OFF_AW    + BB*NCH;
static constexpr size_t OFF_W1    = OFF_EW    + BB*NCH;
static constexpr size_t OFF_W2T   = OFF_W1    + (size_t)BB*MM*HH;
static constexpr size_t OFF_B1    = OFF_W2T   + 2ull*BB*MM*HH;
static constexpr size_t OFF_B2    = OFF_B1    + BB*MM;
static constexpr size_t OFF_ACT   = OFF_B2    + BB*HH;
static constexpr size_t OFF_USP   = OFF_ACT   + (size_t)BB*CC*MM;
static constexpr size_t OFF_AM    = OFF_USP   + BB*8*HH;
static constexpr size_t TOTAL_F   = OFF_AM    + 2ull*BB*MM;

__device__ float g_blob[TOTAL_F];

__device__ __forceinline__ float gelu_exact(float x) {
    return 0.5f * x * (1.0f + erff(x * 0.7071067811865476f));
}
__device__ __forceinline__ float softplus_f(float x) {
    return fmaxf(x, 0.0f) + log1pf(expf(-fabsf(x)));
}
__device__ __forceinline__ float sigmoid_f(float x) {
    return 1.0f / (1.0f + expf(-x));
}
__device__ __forceinline__ float warpSum(float v) {
    #pragma unroll
    for (int o = 16; o > 0; o >>= 1) v += __shfl_down_sync(0xffffffffu, v, o);
    return v;
}

// ---------------- generic fp32 SGEMM: C[M,N]=A[M,K]@B[K,N] ----------------
// 128x128 tile, BK=16, 256 threads, 8x8 per thread. M%128==0, K%16==0 required.
// epi: 0 none, 1 softplus, 2 multiply by sigmoid(gate[r*N+c]).
__global__ __launch_bounds__(256, 2)
void sgemm_kernel(const float* __restrict__ A, const float* __restrict__ B,
                  float* __restrict__ C, int M, int N, int K,
                  const float* __restrict__ gate, int epi)
{
    __shared__ float As[16][128];
    __shared__ float Bs[16][128];
    const int tid = threadIdx.x;
    const int row0 = blockIdx.y * 128;
    const int col0 = blockIdx.x * 128;
    const int tx = tid & 15, ty = tid >> 4;

    float acc[8][8];
    #pragma unroll
    for (int i = 0; i < 8; i++)
        #pragma unroll
        for (int j = 0; j < 8; j++) acc[i][j] = 0.f;

    const int aRow = tid >> 2;
    const int aK   = (tid & 3) * 4;

    for (int k0 = 0; k0 < K; k0 += 16) {
        #pragma unroll
        for (int i = 0; i < 2; i++) {
            int r = aRow + i * 64;
            float4 v = *(const float4*)(A + (size_t)(row0 + r) * K + k0 + aK);
            As[aK + 0][r] = v.x; As[aK + 1][r] = v.y;
            As[aK + 2][r] = v.z; As[aK + 3][r] = v.w;
        }
        #pragma unroll
        for (int i = 0; i < 8; i++) {
            int idx = tid + i * 256;
            int kk = idx >> 7, c = idx & 127;
            float v = 0.f;
            if (col0 + c < N) v = B[(size_t)(k0 + kk) * N + col0 + c];
            Bs[kk][c] = v;
        }
        __syncthreads();
        #pragma unroll
        for (int kk = 0; kk < 16; kk++) {
            float a[8], b[8];
            #pragma unroll
            for (int i = 0; i < 8; i++) a[i] = As[kk][ty * 8 + i];
            #pragma unroll
            for (int j = 0; j < 8; j++) b[j] = Bs[kk][tx * 8 + j];
            #pragma unroll
            for (int i = 0; i < 8; i++)
                #pragma unroll
                for (int j = 0; j < 8; j++) acc[i][j] = fmaf(a[i], b[j], acc[i][j]);
        }
        __syncthreads();
    }
    #pragma unroll
    for (int i = 0; i < 8; i++) {
        int r = row0 + ty * 8 + i;
        #pragma unroll
        for (int j = 0; j < 8; j++) {
            int c = col0 + tx * 8 + j;
            if (c < N) {
                float v = acc[i][j];
                if (epi == 1)      v = softplus_f(v);
                else if (epi == 2) v *= sigmoid_f(gate[(size_t)r * N + c]);
                C[(size_t)r * N + c] = v;
            }
        }
    }
}

// ---------------- eta/alpha at chunk-last rows only ----------------
__global__ void etaalpha_kernel(const float* __restrict__ x,
    const float* __restrict__ We1, const float* __restrict__ We2,
    const float* __restrict__ Wa1, const float* __restrict__ Wa2,
    float* __restrict__ eta_last, float* __restrict__ alpha_last,
    float* __restrict__ awb, float* __restrict__ ewb)
{
    const int bn = blockIdx.x;              // b*64+n
    const int b = bn >> 6, n = bn & 63;
    const float* xr = x + ((size_t)b * SS + n * CC + (CC - 1)) * DD;
    const int tid = threadIdx.x;            // 128 threads
    __shared__ float re2[2][64], ra2[2][64];
    __shared__ float re[64], ra[64];
    __shared__ float red[4];

    const int r = tid & 63, part = tid >> 6;
    float se = 0.f, sa = 0.f;
    for (int d = part * 512; d < part * 512 + 512; d++) {
        float xv = xr[d];
        se = fmaf(xv, We1[d * RR + r], se);
        sa = fmaf(xv, Wa1[d * RR + r], sa);
    }
    re2[part][r] = se; ra2[part][r] = sa;
    __syncthreads();
    if (tid < 64) { re[tid] = re2[0][tid] + re2[1][tid]; ra[tid] = ra2[0][tid] + ra2[1][tid]; }
    __syncthreads();

    float ee = 0.f, aa = 0.f;
    #pragma unroll 8
    for (int rr = 0; rr < 64; rr++) {
        ee = fmaf(re[rr], We2[rr * HH + tid], ee);
        aa = fmaf(ra[rr], Wa2[rr * HH + tid], aa);
    }
    float ev = softplus_f(ee);
    float av = sigmoid_f(aa);
    eta_last[bn * HH + tid] = ev;
    alpha_last[bn * HH + tid] = av;

    float s = warpSum(av);
    if ((tid & 31) == 0) red[tid >> 5] = s;
    __syncthreads();
    if (tid == 0) awb[bn] = (red[0] + red[1] + red[2] + red[3]) * (1.f / HH);
    __syncthreads();
    s = warpSum(ev);
    if ((tid & 31) == 0) red[tid >> 5] = s;
    __syncthreads();
    if (tid == 0) ewb[bn] = (red[0] + red[1] + red[2] + red[3]) * (1.f / HH);
}

// ---------------- causal dwconv(4) for k,v + LN(k) ----------------
__device__ __forceinline__ float blockSum128(float v, float* red) {
    v = warpSum(v);
    int lane = threadIdx.x & 31, w = threadIdx.x >> 5;
    if (lane == 0) red[w] = v;
    __syncthreads();
    float s = red[0] + red[1] + red[2] + red[3];
    __syncthreads();
    return s;
}

__global__ void convln_kernel(const float* __restrict__ kraw, const float* __restrict__ vraw,
    const float* __restrict__ conv_w, const float* __restrict__ conv_b,
    const float* __restrict__ kn_g, const float* __restrict__ kn_b,
    float* __restrict__ kout, float* __restrict__ vout)
{
    const int bs = blockIdx.x;
    const int s = bs & (SS - 1);
    const int h = threadIdx.x;
    const size_t base = (size_t)bs * HH + h;
    __shared__ float red[4];

    float w0 = conv_w[h * 4 + 0], w1 = conv_w[h * 4 + 1];
    float w2 = conv_w[h * 4 + 2], w3 = conv_w[h * 4 + 3];
    float cb = conv_b[h];
    float kc = cb, vc = cb;
    kc = fmaf(w3, kraw[base], kc);            vc = fmaf(w3, vraw[base], vc);
    if (s >= 1) { kc = fmaf(w2, kraw[base - HH],   kc); vc = fmaf(w2, vraw[base - HH],   vc); }
    if (s >= 2) { kc = fmaf(w1, kraw[base - 2*HH], kc); vc = fmaf(w1, vraw[base - 2*HH], vc); }
    if (s >= 3) { kc = fmaf(w0, kraw[base - 3*HH], kc); vc = fmaf(w0, vraw[base - 3*HH], vc); }

    float mean = blockSum128(kc, red) * (1.f / HH);
    float d = kc - mean;
    float var = blockSum128(d * d, red) * (1.f / HH);
    kout[base] = d * rsqrtf(var + 1e-5f) * kn_g[h] + kn_b[h];
    vout[base] = vc;
}

// ---------------- state init ----------------
__global__ void init_state_kernel(const float* __restrict__ mW1, const float* __restrict__ mb1,
                                  const float* __restrict__ mW2, const float* __restrict__ mb2,
                                  float* __restrict__ W1, float* __restrict__ W2T,
                                  float* __restrict__ b1, float* __restrict__ b2)
{
    int i = blockIdx.x * 256 + threadIdx.x;
    if (i < BB * MM * HH) {
        int mh = i % (MM * HH);
        int m = mh >> 7, h = mh & 127;
        W1[i]  = mW1[mh];
        W2T[i] = mW2[h * MM + m];
    }
    if (i < BB * MM) b1[i] = mb1[i % MM];
    if (i < BB * HH) b2[i] = mb2[i % HH];
}

// ---------------- scan kernel A: deferred state update + inter/gelu ----------------
// grid (20, B). bx 0..15: inter blocks (16 m-cols each). bx 16..19: W2T update.
__global__ __launch_bounds__(256)
void chunkA_kernel(int t,
    const float* __restrict__ kbuf, const float* __restrict__ eta_last,
    const float* __restrict__ alpha_last, const float* __restrict__ awb,
    const float* __restrict__ ewb,
    float* __restrict__ W1, float* __restrict__ W2T,
    float* __restrict__ b1, float* __restrict__ b2,
    float* __restrict__ act, const float* __restrict__ us_part,
    float* __restrict__ am)
{
    const int b = blockIdx.y;
    const int bx = blockIdx.x;
    const int tid = threadIdx.x;

    if (bx >= 16) {                      // W2T + b2 deferred update
        if (t == 0) return;
        __shared__ float us_u[HH];
        if (tid < HH) {
            float s = 0.f;
            #pragma unroll
            for (int rb = 0; rb < 8; rb++) s += us_part[(b * 8 + rb) * HH + tid];
            us_u[tid] = s * (1.f / CC);
        }
        __syncthreads();
        const float awv = awb[b * NCH + (t - 1)];
        const float ewv = ewb[b * NCH + (t - 1)];
        const int slice = bx - 16;
        const float* oldW2 = W2T + ((size_t)(((t - 1) & 1) * BB + b)) * (MM * HH);
        float*       newW2 = W2T + ((size_t)(((t)     & 1) * BB + b)) * (MM * HH);
        const float* amo = am + ((t - 1) & 1) * (BB * MM) + b * MM;
        for (int i = tid; i < 64 * HH; i += 256) {
            int m = slice * 64 + (i >> 7);
            int h = i & 127;
            newW2[m * HH + h] = awv * oldW2[m * HH + h] - ewv * us_u[h] * amo[m];
        }
        if (slice == 0 && tid < HH) {
            float ab = alpha_last[(b * NCH + t - 1) * HH + tid];
            float eb = eta_last[(b * NCH + t - 1) * HH + tid];
            b2[b * HH + tid] = ab * b2[b * HH + tid] - eb * us_u[tid];
        }
        return;
    }

    // ---- inter block ----
    __shared__ float W1s[16][129];
    __shared__ float kcs[CC][HH];
    __shared__ float b1s[16];
    __shared__ float us_s[HH];
    __shared__ float sus2_s;
    __shared__ float amred[16][17];

    const int m0 = bx * 16;
    float* W1g = W1 + (size_t)b * (MM * HH) + m0 * HH;
    float* b1g = b1 + b * MM + m0;

    if (t == 0) {
        for (int i = tid; i < 16 * HH; i += 256) W1s[i >> 7][i & 127] = W1g[i];
        if (tid < 16) b1s[tid] = b1g[tid];
    } else {
        if (tid < HH) {
            float s = 0.f;
            #pragma unroll
            for (int rb = 0; rb < 8; rb++) s += us_part[(b * 8 + rb) * HH + tid];
            us_s[tid] = s * (1.f / CC);
        }
        __syncthreads();
        if (tid < 32) {
            float s = 0.f;
            for (int i = tid; i < HH; i += 32) s += us_s[i] * us_s[i];
            s = warpSum(s);
            if (tid == 0) sus2_s = s;
        }
        __syncthreads();
        const float awv = awb[b * NCH + (t - 1)];
        const float ewv = ewb[b * NCH + (t - 1)];
        const float sus2 = sus2_s;
        const float* amo = am + ((t - 1) & 1) * (BB * MM) + b * MM + m0;
        for (int i = tid; i < 16 * HH; i += 256) {
            int m = i >> 7, h = i & 127;
            float w = awv * W1g[i] - ewv * amo[m] * us_s[h];
            W1g[i] = w;
            W1s[m][h] = w;
        }
        // b1 update: b1u[m] = aw*sum_h us*W2old[m,h] - ew*sus2*am[m]
        const float* oldW2 = W2T + ((size_t)(((t - 1) & 1) * BB + b)) * (MM * HH);
        int lane = tid & 31, wp = tid >> 5;
        #pragma unroll
        for (int q = 0; q < 2; q++) {
            int mm = wp * 2 + q;
            int m = m0 + mm;
            float s = 0.f;
            #pragma unroll
            for (int k = 0; k < 4; k++) {
                int h = lane + k * 32;
                s = fmaf(us_s[h], oldW2[m * HH + h], s);
            }
            s = warpSum(s);
            if (lane == 0) {
                float b1u = awv * s - ewv * sus2 * amo[mm];
                float nb1 = awv * b1g[mm] - ewv * b1u;
                b1g[mm] = nb1;
                b1s[mm] = nb1;
            }
        }
    }
    __syncthreads();

    const float* kc = kbuf + ((size_t)b * SS + t * CC) * HH;
    for (int i = tid; i < CC * HH; i += 256) kcs[i >> 7][i & 127] = kc[i];
    __syncthreads();

    const int m  = tid & 15;
    const int rg = tid >> 4;      // 16 groups of 4 rows
    float a0 = 0.f, a1 = 0.f, a2 = 0.f, a3 = 0.f;
    #pragma unroll 4
    for (int h = 0; h < HH; h++) {
        float w = W1s[m][h];
        a0 = fmaf(kcs[rg * 4 + 0][h], w, a0);
        a1 = fmaf(kcs[rg * 4 + 1][h], w, a1);
        a2 = fmaf(kcs[rg * 4 + 2][h], w, a2);
        a3 = fmaf(kcs[rg * 4 + 3][h], w, a3);
    }
    const float b1v = b1s[m];
    float vals[4] = {a0, a1, a2, a3};
    float amp = 0.f;
    float* actp = act + (size_t)b * (CC * MM) + (size_t)(rg * 4) * MM + m0 + m;
    #pragma unroll
    for (int i = 0; i < 4; i++) {
        float g = gelu_exact(vals[i] + b1v);
        actp[(size_t)i * MM] = g;
        amp += g;
    }
    amred[m][rg] = amp;
    __syncthreads();
    if (tid < 16) {
        float s = 0.f;
        #pragma unroll
        for (int r = 0; r < 16; r++) s += amred[tid][r];
        am[(t & 1) * (BB * MM) + b * MM + m0 + tid] = s * (1.f / CC);
    }
}

// ---------------- scan kernel B: out = act@W2T + b2, grad, us partials ----------------
// grid (8, B): 8 row-groups of 8 rows. 256 threads: h = tid&127, half = tid>>7 (4 rows).
__global__ __launch_bounds__(256)
void chunkB_kernel(int t,
    const float* __restrict__ vbuf, const float* __restrict__ delta,
    const float* __restrict__ act, const float* __restrict__ W2T,
    const float* __restrict__ b2,
    float* __restrict__ comb, float* __restrict__ us_part)
{
    const int b = blockIdx.y;
    const int rg = blockIdx.x;
    const int tid = threadIdx.x;
    const int h = tid & 127;
    const int half = tid >> 7;

    __shared__ float acts[8][MM];
    __shared__ float enred[8][4];
    __shared__ float us_s[HH];

    const float* actg = act + (size_t)b * (CC * MM) + (size_t)(rg * 8) * MM;
    for (int i = tid; i < 8 * MM; i += 256) acts[i >> 8][i & 255] = actg[i];
    __syncthreads();

    const float* w2 = W2T + ((size_t)((t & 1) * BB + b)) * (MM * HH);
    float o0 = 0.f, o1 = 0.f, o2 = 0.f, o3 = 0.f;
    const int r0 = half * 4;
    #pragma unroll 8
    for (int m = 0; m < MM; m++) {
        float w = __ldg(w2 + (size_t)m * HH + h);
        o0 = fmaf(acts[r0 + 0][m], w, o0);
        o1 = fmaf(acts[r0 + 1][m], w, o1);
        o2 = fmaf(acts[r0 + 2][m], w, o2);
        o3 = fmaf(acts[r0 + 3][m], w, o3);
    }
    const float b2v = b2[b * HH + h];
    float out[4] = {o0 + b2v, o1 + b2v, o2 + b2v, o3 + b2v};

    const size_t rowbase = (size_t)b * SS + (size_t)t * CC + rg * 8 + r0;
    float err[4];
    #pragma unroll
    for (int i = 0; i < 4; i++) {
        size_t idx = (rowbase + i) * HH + h;
        comb[idx] = out[i];
        err[i] = out[i] - vbuf[idx];
        float e2 = warpSum(err[i] * err[i]);
        if ((tid & 31) == 0) enred[r0 + i][(tid >> 5) & 3] = e2;
    }
    __syncthreads();

    float gs = 0.f;
    #pragma unroll
    for (int i = 0; i < 4; i++) {
        float en = sqrtf(enred[r0 + i][0] + enred[r0 + i][1] +
                         enred[r0 + i][2] + enred[r0 + i][3]);
        float dc = delta[(rowbase + i) * HH + h];
        float g = (en > dc) ? dc * err[i] / (en + 1e-9f) : err[i];
        gs += g;
    }
    if (half == 0) us_s[h] = gs;
    __syncthreads();
    if (half == 1) us_part[(b * 8 + rg) * HH + h] = us_s[h] + gs;
}

// ---------------- launch ----------------
extern "C" void kernel_launch(void* const* d_in, const int* in_sizes, int n_in,
                              void* d_out, int out_size)
{
    const float* x      = (const float*)d_in[0];
    const float* Wk     = (const float*)d_in[2];
    const float* Wv     = (const float*)d_in[3];
    const float* Wo     = (const float*)d_in[4];
    const float* Wg     = (const float*)d_in[5];
    const float* We1    = (const float*)d_in[6];
    const float* We2    = (const float*)d_in[7];
    const float* Wd1    = (const float*)d_in[8];
    const float* Wd2    = (const float*)d_in[9];
    const float* Wa1    = (const float*)d_in[10];
    const float* Wa2    = (const float*)d_in[11];
    const float* conv_w = (const float*)d_in[12];
    const float* conv_b = (const float*)d_in[13];
    const float* kn_g   = (const float*)d_in[16];
    const float* kn_b   = (const float*)d_in[17];
    const float* mW1    = (const float*)d_in[18];
    const float* mb1    = (const float*)d_in[19];
    const float* mW2    = (const float*)d_in[20];
    const float* mb2    = (const float*)d_in[21];
    float* out = (float*)d_out;

    float* blob = nullptr;
    cudaGetSymbolAddress((void**)&blob, g_blob);

    float* kraw   = blob + OFF_KRAW;
    float* vraw   = blob + OFF_VRAW;
    float* kbuf   = blob + OFF_K;
    float* vbuf   = blob + OFF_V;
    float* delta  = blob + OFF_DELTA;
    float* comb   = blob + OFF_COMB;
    float* rd     = blob + OFF_RD;
    float* gate   = blob + OFF_GATE;
    float* eta_l  = blob + OFF_ETA;
    float* alph_l = blob + OFF_ALPHA;
    float* awb    = blob + OFF_AW;
    float* ewb    = blob + OFF_EW;
    float* W1     = blob + OFF_W1;
    float* W2T    = blob + OFF_W2T;
    float* b1     = blob + OFF_B1;
    float* b2     = blob + OFF_B2;
    float* act    = blob + OFF_ACT;
    float* usp    = blob + OFF_USP;
    float* am     = blob + OFF_AM;

    const int MROWS = BB * SS;          // 16384
    dim3 blk(256);

    // eta/alpha at chunk-last rows
    etaalpha_kernel<<<BB * NCH, 128>>>(x, We1, We2, Wa1, Wa2, eta_l, alph_l, awb, ewb);

    // projections
    sgemm_kernel<<<dim3(1, MROWS / 128), blk>>>(x, Wk, kraw, MROWS, HH, DD, nullptr, 0);
    sgemm_kernel<<<dim3(1, MROWS / 128), blk>>>(x, Wv, vraw, MROWS, HH, DD, nullptr, 0);
    sgemm_kernel<<<dim3(1, MROWS / 128), blk>>>(x, Wd1, rd,  MROWS, RR, DD, nullptr, 0);
    sgemm_kernel<<<dim3(1, MROWS / 128), blk>>>(rd, Wd2, delta, MROWS, HH, RR, nullptr, 1);
    sgemm_kernel<<<dim3(DD / 128, MROWS / 128), blk>>>(x, Wg, gate, MROWS, DD, DD, nullptr, 0);

    // conv + LN
    convln_kernel<<<BB * SS, HH>>>(kraw, vraw, conv_w, conv_b, kn_g, kn_b, kbuf, vbuf);

    // init memory state
    init_state_kernel<<<(BB * MM * HH + 255) / 256, 256>>>(mW1, mb1, mW2, mb2, W1, W2T, b1, b2);

    // sequential scan over 64 chunks
    for (int t = 0; t < NCH; t++) {
        chunkA_kernel<<<dim3(20, BB), blk>>>(t, kbuf, eta_l, alph_l, awb, ewb,
                                             W1, W2T, b1, b2, act, usp, am);
        chunkB_kernel<<<dim3(8, BB), blk>>>(t, vbuf, delta, act, W2T, b2, comb, usp);
    }

    // final: out = (comb @ Wo) * sigmoid(gate)
    sgemm_kernel<<<dim3(DD / 128, MROWS / 128), blk>>>(comb, Wo, out, MROWS, DD, HH, gate, 2);
}

// round 16
// speedup vs baseline: 1.0047x; 1.0021x over previous
#include <cuda_runtime.h>
#include <cuda_bf16.h>
#include <math.h>

#define BB 4
#define SS 4096
#define DD 1024
#define HH 128
#define MM 256
#define RR 64
#define CC 64
#define NCH 64

static constexpr size_t SZ_BSH  = (size_t)BB*SS*HH;
static constexpr size_t OFF_KRAW  = 0;
static constexpr size_t OFF_VRAW  = OFF_KRAW  + SZ_BSH;
static constexpr size_t OFF_K     = OFF_VRAW  + SZ_BSH;
static constexpr size_t OFF_V     = OFF_K     + SZ_BSH;
static constexpr size_t OFF_DELTA = OFF_V     + SZ_BSH;
static constexpr size_t OFF_COMB  = OFF_DELTA + SZ_BSH;
static constexpr size_t OFF_RD    = OFF_COMB  + SZ_BSH;
static constexpr size_t OFF_GATE  = OFF_RD    + (size_t)BB*SS*RR;
static constexpr size_t OFF_ETA   = OFF_GATE  + (size_t)BB*SS*DD;
static constexpr size_t OFF_ALPHA = OFF_ETA   + (size_t)BB*NCH*HH;
static constexpr size_t OFF_AW    = OFF_ALPHA + (size_t)BB*NCH*HH;
static constexpr size_t OFF_EW    = OFF_AW    + BB*NCH;
static constexpr size_t OFF_W1    = OFF_EW    + BB*NCH;
static constexpr size_t OFF_W2T   = OFF_W1    + (size_t)BB*MM*HH;
static constexpr size_t OFF_B1    = OFF_W2T   + 2ull*BB*MM*HH;
static constexpr size_t OFF_B2    = OFF_B1    + BB*MM;
static constexpr size_t OFF_ACT   = OFF_B2    + BB*HH;
static constexpr size_t OFF_USP   = OFF_ACT   + (size_t)BB*CC*MM;
static constexpr size_t OFF_AM    = OFF_USP   + BB*8*HH;
static constexpr size_t TOTAL_F   = OFF_AM    + 2ull*BB*MM;

__device__ float g_blob[TOTAL_F];

__device__ __forceinline__ float gelu_exact(float x) {
    return 0.5f * x * (1.0f + erff(x * 0.7071067811865476f));
}
__device__ __forceinline__ float softplus_f(float x) {
    return fmaxf(x, 0.0f) + log1pf(expf(-fabsf(x)));
}
__device__ __forceinline__ float sigmoid_f(float x) {
    return 1.0f / (1.0f + expf(-x));
}
__device__ __forceinline__ float warpSum(float v) {
    #pragma unroll
    for (int o = 16; o > 0; o >>= 1) v += __shfl_down_sync(0xffffffffu, v, o);
    return v;
}

// ---------------- generic fp32 SGEMM: C[M,N]=A[M,K]@B[K,N] ----------------
// 128x128 tile, BK=16, 256 threads, 8x8 per thread. M%128==0, K%16==0 required.
// epi: 0 none, 1 softplus, 2 multiply by sigmoid(gate[r*N+c]).
__global__ __launch_bounds__(256, 2)
void sgemm_kernel(const float* __restrict__ A, const float* __restrict__ B,
                  float* __restrict__ C, int M, int N, int K,
                  const float* __restrict__ gate, int epi)
{
    __shared__ float As[16][128];
    __shared__ float Bs[16][128];
    const int tid = threadIdx.x;
    const int row0 = blockIdx.y * 128;
    const int col0 = blockIdx.x * 128;
    const int tx = tid & 15, ty = tid >> 4;

    float acc[8][8];
    #pragma unroll
    for (int i = 0; i < 8; i++)
        #pragma unroll
        for (int j = 0; j < 8; j++) acc[i][j] = 0.f;

    const int aRow = tid >> 2;
    const int aK   = (tid & 3) * 4;

    for (int k0 = 0; k0 < K; k0 += 16) {
        #pragma unroll
        for (int i = 0; i < 2; i++) {
            int r = aRow + i * 64;
            float4 v = *(const float4*)(A + (size_t)(row0 + r) * K + k0 + aK);
            As[aK + 0][r] = v.x; As[aK + 1][r] = v.y;
            As[aK + 2][r] = v.z; As[aK + 3][r] = v.w;
        }
        #pragma unroll
        for (int i = 0; i < 8; i++) {
            int idx = tid + i * 256;
            int kk = idx >> 7, c = idx & 127;
            float v = 0.f;
            if (col0 + c < N) v = B[(size_t)(k0 + kk) * N + col0 + c];
            Bs[kk][c] = v;
        }
        __syncthreads();
        #pragma unroll
        for (int kk = 0; kk < 16; kk++) {
            float a[8], b[8];
            #pragma unroll
            for (int i = 0; i < 8; i++) a[i] = As[kk][ty * 8 + i];
            #pragma unroll
            for (int j = 0; j < 8; j++) b[j] = Bs[kk][tx * 8 + j];
            #pragma unroll
            for (int i = 0; i < 8; i++)
                #pragma unroll
                for (int j = 0; j < 8; j++) acc[i][j] = fmaf(a[i], b[j], acc[i][j]);
        }
        __syncthreads();
    }
    #pragma unroll
    for (int i = 0; i < 8; i++) {
        int r = row0 + ty * 8 + i;
        #pragma unroll
        for (int j = 0; j < 8; j++) {
            int c = col0 + tx * 8 + j;
            if (c < N) {
                float v = acc[i][j];
                if (epi == 1)      v = softplus_f(v);
                else if (epi == 2) v *= sigmoid_f(gate[(size_t)r * N + c]);
                C[(size_t)r * N + c] = v;
            }
        }
    }
}

// ---------------- eta/alpha at chunk-last rows only ----------------
__global__ void etaalpha_kernel(const float* __restrict__ x,
    const float* __restrict__ We1, const float* __restrict__ We2,
    const float* __restrict__ Wa1, const float* __restrict__ Wa2,
    float* __restrict__ eta_last, float* __restrict__ alpha_last,
    float* __restrict__ awb, float* __restrict__ ewb)
{
    const int bn = blockIdx.x;              // b*64+n
    const int b = bn >> 6, n = bn & 63;
    const float* xr = x + ((size_t)b * SS + n * CC + (CC - 1)) * DD;
    const int tid = threadIdx.x;            // 128 threads
    __shared__ float re2[2][64], ra2[2][64];
    __shared__ float re[64], ra[64];
    __shared__ float red[4];

    const int r = tid & 63, part = tid >> 6;
    float se = 0.f, sa = 0.f;
    for (int d = part * 512; d < part * 512 + 512; d++) {
        float xv = xr[d];
        se = fmaf(xv, We1[d * RR + r], se);
        sa = fmaf(xv, Wa1[d * RR + r], sa);
    }
    re2[part][r] = se; ra2[part][r] = sa;
    __syncthreads();
    if (tid < 64) { re[tid] = re2[0][tid] + re2[1][tid]; ra[tid] = ra2[0][tid] + ra2[1][tid]; }
    __syncthreads();

    float ee = 0.f, aa = 0.f;
    #pragma unroll 8
    for (int rr = 0; rr < 64; rr++) {
        ee = fmaf(re[rr], We2[rr * HH + tid], ee);
        aa = fmaf(ra[rr], Wa2[rr * HH + tid], aa);
    }
    float ev = softplus_f(ee);
    float av = sigmoid_f(aa);
    eta_last[bn * HH + tid] = ev;
    alpha_last[bn * HH + tid] = av;

    float s = warpSum(av);
    if ((tid & 31) == 0) red[tid >> 5] = s;
    __syncthreads();
    if (tid == 0) awb[bn] = (red[0] + red[1] + red[2] + red[3]) * (1.f / HH);
    __syncthreads();
    s = warpSum(ev);
    if ((tid & 31) == 0) red[tid >> 5] = s;
    __syncthreads();
    if (tid == 0) ewb[bn] = (red[0] + red[1] + red[2] + red[3]) * (1.f / HH);
}

// ---------------- causal dwconv(4) for k,v + LN(k) ----------------
__device__ __forceinline__ float blockSum128(float v, float* red) {
    v = warpSum(v);
    int lane = threadIdx.x & 31, w = threadIdx.x >> 5;
    if (lane == 0) red[w] = v;
    __syncthreads();
    float s = red[0] + red[1] + red[2] + red[3];
    __syncthreads();
    return s;
}

__global__ void convln_kernel(const float* __restrict__ kraw, const float* __restrict__ vraw,
    const float* __restrict__ conv_w, const float* __restrict__ conv_b,
    const float* __restrict__ kn_g, const float* __restrict__ kn_b,
    float* __restrict__ kout, float* __restrict__ vout)
{
    const int bs = blockIdx.x;
    const int s = bs & (SS - 1);
    const int h = threadIdx.x;
    const size_t base = (size_t)bs * HH + h;
    __shared__ float red[4];

    float w0 = conv_w[h * 4 + 0], w1 = conv_w[h * 4 + 1];
    float w2 = conv_w[h * 4 + 2], w3 = conv_w[h * 4 + 3];
    float cb = conv_b[h];
    float kc = cb, vc = cb;
    kc = fmaf(w3, kraw[base], kc);            vc = fmaf(w3, vraw[base], vc);
    if (s >= 1) { kc = fmaf(w2, kraw[base - HH],   kc); vc = fmaf(w2, vraw[base - HH],   vc); }
    if (s >= 2) { kc = fmaf(w1, kraw[base - 2*HH], kc); vc = fmaf(w1, vraw[base - 2*HH], vc); }
    if (s >= 3) { kc = fmaf(w0, kraw[base - 3*HH], kc); vc = fmaf(w0, vraw[base - 3*HH], vc); }

    float mean = blockSum128(kc, red) * (1.f / HH);
    float d = kc - mean;
    float var = blockSum128(d * d, red) * (1.f / HH);
    kout[base] = d * rsqrtf(var + 1e-5f) * kn_g[h] + kn_b[h];
    vout[base] = vc;
}

// ---------------- state init ----------------
__global__ void init_state_kernel(const float* __restrict__ mW1, const float* __restrict__ mb1,
                                  const float* __restrict__ mW2, const float* __restrict__ mb2,
                                  float* __restrict__ W1, float* __restrict__ W2T,
                                  float* __restrict__ b1, float* __restrict__ b2)
{
    int i = blockIdx.x * 256 + threadIdx.x;
    if (i < BB * MM * HH) {
        int mh = i % (MM * HH);
        int m = mh >> 7, h = mh & 127;
        W1[i]  = mW1[mh];
        W2T[i] = mW2[h * MM + m];
    }
    if (i < BB * MM) b1[i] = mb1[i % MM];
    if (i < BB * HH) b2[i] = mb2[i % HH];
}

// ---------------- scan kernel A: deferred state update + inter/gelu ----------------
// grid (20, B). bx 0..15: inter blocks (16 m-cols each). bx 16..19: W2T update.
__global__ __launch_bounds__(256)
void chunkA_kernel(int t,
    const float* __restrict__ kbuf, const float* __restrict__ eta_last,
    const float* __restrict__ alpha_last, const float* __restrict__ awb,
    const float* __restrict__ ewb,
    float* __restrict__ W1, float* __restrict__ W2T,
    float* __restrict__ b1, float* __restrict__ b2,
    float* __restrict__ act, const float* __restrict__ us_part,
    float* __restrict__ am)
{
    const int b = blockIdx.y;
    const int bx = blockIdx.x;
    const int tid = threadIdx.x;

    if (bx >= 16) {                      // W2T + b2 deferred update
        if (t == 0) return;
        __shared__ float us_u[HH];
        if (tid < HH) {
            float s = 0.f;
            #pragma unroll
            for (int rb = 0; rb < 8; rb++) s += us_part[(b * 8 + rb) * HH + tid];
            us_u[tid] = s * (1.f / CC);
        }
        __syncthreads();
        const float awv = awb[b * NCH + (t - 1)];
        const float ewv = ewb[b * NCH + (t - 1)];
        const int slice = bx - 16;
        const float* oldW2 = W2T + ((size_t)(((t - 1) & 1) * BB + b)) * (MM * HH);
        float*       newW2 = W2T + ((size_t)(((t)     & 1) * BB + b)) * (MM * HH);
        const float* amo = am + ((t - 1) & 1) * (BB * MM) + b * MM;
        for (int i = tid; i < 64 * HH; i += 256) {
            int m = slice * 64 + (i >> 7);
            int h = i & 127;
            newW2[m * HH + h] = awv * oldW2[m * HH + h] - ewv * us_u[h] * amo[m];
        }
        if (slice == 0 && tid < HH) {
            float ab = alpha_last[(b * NCH + t - 1) * HH + tid];
            float eb = eta_last[(b * NCH + t - 1) * HH + tid];
            b2[b * HH + tid] = ab * b2[b * HH + tid] - eb * us_u[tid];
        }
        return;
    }

    // ---- inter block ----
    __shared__ float W1s[16][129];
    __shared__ float kcs[CC][HH];
    __shared__ float b1s[16];
    __shared__ float us_s[HH];
    __shared__ float sus2_s;
    __shared__ float amred[16][17];

    const int m0 = bx * 16;
    float* W1g = W1 + (size_t)b * (MM * HH) + m0 * HH;
    float* b1g = b1 + b * MM + m0;

    if (t == 0) {
        for (int i = tid; i < 16 * HH; i += 256) W1s[i >> 7][i & 127] = W1g[i];
        if (tid < 16) b1s[tid] = b1g[tid];
    } else {
        if (tid < HH) {
            float s = 0.f;
            #pragma unroll
            for (int rb = 0; rb < 8; rb++) s += us_part[(b * 8 + rb) * HH + tid];
            us_s[tid] = s * (1.f / CC);
        }
        __syncthreads();
        if (tid < 32) {
            float s = 0.f;
            for (int i = tid; i < HH; i += 32) s += us_s[i] * us_s[i];
            s = warpSum(s);
            if (tid == 0) sus2_s = s;
        }
        __syncthreads();
        const float awv = awb[b * NCH + (t - 1)];
        const float ewv = ewb[b * NCH + (t - 1)];
        const float sus2 = sus2_s;
        const float* amo = am + ((t - 1) & 1) * (BB * MM) + b * MM + m0;
        for (int i = tid; i < 16 * HH; i += 256) {
            int m = i >> 7, h = i & 127;
            float w = awv * W1g[i] - ewv * amo[m] * us_s[h];
            W1g[i] = w;
            W1s[m][h] = w;
        }
        // b1 update: b1u[m] = aw*sum_h us*W2old[m,h] - ew*sus2*am[m]
        const float* oldW2 = W2T + ((size_t)(((t - 1) & 1) * BB + b)) * (MM * HH);
        int lane = tid & 31, wp = tid >> 5;
        #pragma unroll
        for (int q = 0; q < 2; q++) {
            int mm = wp * 2 + q;
            int m = m0 + mm;
            float s = 0.f;
            #pragma unroll
            for (int k = 0; k < 4; k++) {
                int h = lane + k * 32;
                s = fmaf(us_s[h], oldW2[m * HH + h], s);
            }
            s = warpSum(s);
            if (lane == 0) {
                float b1u = awv * s - ewv * sus2 * amo[mm];
                float nb1 = awv * b1g[mm] - ewv * b1u;
                b1g[mm] = nb1;
                b1s[mm] = nb1;
            }
        }
    }
    __syncthreads();

    const float* kc = kbuf + ((size_t)b * SS + t * CC) * HH;
    for (int i = tid; i < CC * HH; i += 256) kcs[i >> 7][i & 127] = kc[i];
    __syncthreads();

    const int m  = tid & 15;
    const int rg = tid >> 4;      // 16 groups of 4 rows
    float a0 = 0.f, a1 = 0.f, a2 = 0.f, a3 = 0.f;
    #pragma unroll 4
    for (int h = 0; h < HH; h++) {
        float w = W1s[m][h];
        a0 = fmaf(kcs[rg * 4 + 0][h], w, a0);
        a1 = fmaf(kcs[rg * 4 + 1][h], w, a1);
        a2 = fmaf(kcs[rg * 4 + 2][h], w, a2);
        a3 = fmaf(kcs[rg * 4 + 3][h], w, a3);
    }
    const float b1v = b1s[m];
    float vals[4] = {a0, a1, a2, a3};
    float amp = 0.f;
    float* actp = act + (size_t)b * (CC * MM) + (size_t)(rg * 4) * MM + m0 + m;
    #pragma unroll
    for (int i = 0; i < 4; i++) {
        float g = gelu_exact(vals[i] + b1v);
        actp[(size_t)i * MM] = g;
        amp += g;
    }
    amred[m][rg] = amp;
    __syncthreads();
    if (tid < 16) {
        float s = 0.f;
        #pragma unroll
        for (int r = 0; r < 16; r++) s += amred[tid][r];
        am[(t & 1) * (BB * MM) + b * MM + m0 + tid] = s * (1.f / CC);
    }
}

// ---------------- scan kernel B: out = act@W2T + b2, grad, us partials ----------------
// grid (8, B): 8 row-groups of 8 rows. 256 threads: h = tid&127, half = tid>>7 (4 rows).
__global__ __launch_bounds__(256)
void chunkB_kernel(int t,
    const float* __restrict__ vbuf, const float* __restrict__ delta,
    const float* __restrict__ act, const float* __restrict__ W2T,
    const float* __restrict__ b2,
    float* __restrict__ comb, float* __restrict__ us_part)
{
    const int b = blockIdx.y;
    const int rg = blockIdx.x;
    const int tid = threadIdx.x;
    const int h = tid & 127;
    const int half = tid >> 7;

    __shared__ float acts[8][MM];
    __shared__ float enred[8][4];
    __shared__ float us_s[HH];

    const float* actg = act + (size_t)b * (CC * MM) + (size_t)(rg * 8) * MM;
    for (int i = tid; i < 8 * MM; i += 256) acts[i >> 8][i & 255] = actg[i];
    __syncthreads();

    const float* w2 = W2T + ((size_t)((t & 1) * BB + b)) * (MM * HH);
    float o0 = 0.f, o1 = 0.f, o2 = 0.f, o3 = 0.f;
    const int r0 = half * 4;
    #pragma unroll 8
    for (int m = 0; m < MM; m++) {
        float w = __ldg(w2 + (size_t)m * HH + h);
        o0 = fmaf(acts[r0 + 0][m], w, o0);
        o1 = fmaf(acts[r0 + 1][m], w, o1);
        o2 = fmaf(acts[r0 + 2][m], w, o2);
        o3 = fmaf(acts[r0 + 3][m], w, o3);
    }
    const float b2v = b2[b * HH + h];
    float out[4] = {o0 + b2v, o1 + b2v, o2 + b2v, o3 + b2v};

    const size_t rowbase = (size_t)b * SS + (size_t)t * CC + rg * 8 + r0;
    float err[4];
    #pragma unroll
    for (int i = 0; i < 4; i++) {
        size_t idx = (rowbase + i) * HH + h;
        comb[idx] = out[i];
        err[i] = out[i] - vbuf[idx];
        float e2 = warpSum(err[i] * err[i]);
        if ((tid & 31) == 0) enred[r0 + i][(tid >> 5) & 3] = e2;
    }
    __syncthreads();

    float gs = 0.f;
    #pragma unroll
    for (int i = 0; i < 4; i++) {
        float en = sqrtf(enred[r0 + i][0] + enred[r0 + i][1] +
                         enred[r0 + i][2] + enred[r0 + i][3]);
        float dc = delta[(rowbase + i) * HH + h];
        float g = (en > dc) ? dc * err[i] / (en + 1e-9f) : err[i];
        gs += g;
    }
    if (half == 0) us_s[h] = gs;
    __syncthreads();
    if (half == 1) us_part[(b * 8 + rg) * HH + h] = us_s[h] + gs;
}

// ---------------- launch ----------------
extern "C" void kernel_launch(void* const* d_in, const int* in_sizes, int n_in,
                              void* d_out, int out_size)
{
    const float* x      = (const float*)d_in[0];
    const float* Wk     = (const float*)d_in[2];
    const float* Wv     = (const float*)d_in[3];
    const float* Wo     = (const float*)d_in[4];
    const float* Wg     = (const float*)d_in[5];
    const float* We1    = (const float*)d_in[6];
    const float* We2    = (const float*)d_in[7];
    const float* Wd1    = (const float*)d_in[8];
    const float* Wd2    = (const float*)d_in[9];
    const float* Wa1    = (const float*)d_in[10];
    const float* Wa2    = (const float*)d_in[11];
    const float* conv_w = (const float*)d_in[12];
    const float* conv_b = (const float*)d_in[13];
    const float* kn_g   = (const float*)d_in[16];
    const float* kn_b   = (const float*)d_in[17];
    const float* mW1    = (const float*)d_in[18];
    const float* mb1    = (const float*)d_in[19];
    const float* mW2    = (const float*)d_in[20];
    const float* mb2    = (const float*)d_in[21];
    float* out = (float*)d_out;

    float* blob = nullptr;
    cudaGetSymbolAddress((void**)&blob, g_blob);

    float* kraw   = blob + OFF_KRAW;
    float* vraw   = blob + OFF_VRAW;
    float* kbuf   = blob + OFF_K;
    float* vbuf   = blob + OFF_V;
    float* delta  = blob + OFF_DELTA;
    float* comb   = blob + OFF_COMB;
    float* rd     = blob + OFF_RD;
    float* gate   = blob + OFF_GATE;
    float* eta_l  = blob + OFF_ETA;
    float* alph_l = blob + OFF_ALPHA;
    float* awb    = blob + OFF_AW;
    float* ewb    = blob + OFF_EW;
    float* W1     = blob + OFF_W1;
    float* W2T    = blob + OFF_W2T;
    float* b1     = blob + OFF_B1;
    float* b2     = blob + OFF_B2;
    float* act    = blob + OFF_ACT;
    float* usp    = blob + OFF_USP;
    float* am     = blob + OFF_AM;

    const int MROWS = BB * SS;          // 16384
    dim3 blk(256);

    // eta/alpha at chunk-last rows
    etaalpha_kernel<<<BB * NCH, 128>>>(x, We1, We2, Wa1, Wa2, eta_l, alph_l, awb, ewb);

    // projections
    sgemm_kernel<<<dim3(1, MROWS / 128), blk>>>(x, Wk, kraw, MROWS, HH, DD, nullptr, 0);
    sgemm_kernel<<<dim3(1, MROWS / 128), blk>>>(x, Wv, vraw, MROWS, HH, DD, nullptr, 0);
    sgemm_kernel<<<dim3(1, MROWS / 128), blk>>>(x, Wd1, rd,  MROWS, RR, DD, nullptr, 0);
    sgemm_kernel<<<dim3(1, MROWS / 128), blk>>>(rd, Wd2, delta, MROWS, HH, RR, nullptr, 1);
    sgemm_kernel<<<dim3(DD / 128, MROWS / 128), blk>>>(x, Wg, gate, MROWS, DD, DD, nullptr, 0);

    // conv + LN
    convln_kernel<<<BB * SS, HH>>>(kraw, vraw, conv_w, conv_b, kn_g, kn_b, kbuf, vbuf);

    // init memory state
    init_state_kernel<<<(BB * MM * HH + 255) / 256, 256>>>(mW1, mb1, mW2, mb2, W1, W2T, b1, b2);

    // sequential scan over 64 chunks
    for (int t = 0; t < NCH; t++) {
        chunkA_kernel<<<dim3(20, BB), blk>>>(t, kbuf, eta_l, alph_l, awb, ewb,
                                             W1, W2T, b1, b2, act, usp, am);
        chunkB_kernel<<<dim3(8, BB), blk>>>(t, vbuf, delta, act, W2T, b2, comb, usp);
    }

    // final: out = (comb @ Wo) * sigmoid(gate)
    sgemm_kernel<<<dim3(DD / 128, MROWS / 128), blk>>>(comb, Wo, out, MROWS, DD, HH, gate, 2);
}